// round 1
// baseline (speedup 1.0000x reference)
#include <cuda_runtime.h>

#define KV 16
#define DIM 15
#define NPIX (2048 * 2048)
#define TPB 256
#define PPT 4   // pixels per thread

// t = b_k - 2 * v_k . z  (monotone transform of squared distance, per pixel)
// argmin_k t_k == argmin_k dist_k ;  dmin = sqrt(max(zz + t_min, 0))

__global__ __launch_bounds__(TPB) void gum_kernel(const float* __restrict__ z,
                                                  const float* __restrict__ v,
                                                  float* __restrict__ out) {
    __shared__ float ws[DIM][KV];   // ws[j][k] = -2 * v[k][j]
    __shared__ float bs[KV];        // bs[k]    = ||v_k||^2

    const int t = threadIdx.x;
    if (t < KV * DIM) {
        int k = t / DIM;
        int j = t - k * DIM;
        ws[j][k] = -2.0f * v[t];
    }
    if (t < KV) {
        float s = 0.0f;
        #pragma unroll
        for (int j = 0; j < DIM; ++j) {
            float a = v[t * DIM + j];
            s = fmaf(a, a, s);
        }
        bs[t] = s;
    }
    __syncthreads();

    const int i = (blockIdx.x * TPB + t) * PPT;

    float4 acc[KV];
    #pragma unroll
    for (int k = 0; k < KV; ++k) {
        float b = bs[k];
        acc[k] = make_float4(b, b, b, b);
    }

    float4 zz = make_float4(0.f, 0.f, 0.f, 0.f);

    #pragma unroll
    for (int j = 0; j < DIM; ++j) {
        float4 zv = *reinterpret_cast<const float4*>(z + (size_t)j * NPIX + i);
        zz.x = fmaf(zv.x, zv.x, zz.x);
        zz.y = fmaf(zv.y, zv.y, zz.y);
        zz.z = fmaf(zv.z, zv.z, zz.z);
        zz.w = fmaf(zv.w, zv.w, zz.w);
        #pragma unroll
        for (int k = 0; k < KV; ++k) {
            float w = ws[j][k];
            acc[k].x = fmaf(w, zv.x, acc[k].x);
            acc[k].y = fmaf(w, zv.y, acc[k].y);
            acc[k].z = fmaf(w, zv.z, acc[k].z);
            acc[k].w = fmaf(w, zv.w, acc[k].w);
        }
    }

    float4 xo, dm;

    // Per-component argmin (strict <, first-wins: matches jnp.argmin ties)
    #define REDUCE(comp)                                              \
    {                                                                 \
        float bv = acc[0].comp;                                       \
        int bk = 0;                                                   \
        _Pragma("unroll")                                             \
        for (int k = 1; k < KV; ++k) {                                \
            if (acc[k].comp < bv) { bv = acc[k].comp; bk = k; }       \
        }                                                             \
        xo.comp = (float)bk;                                          \
        dm.comp = sqrtf(fmaxf(zz.comp + bv, 0.0f));                   \
    }

    REDUCE(x)
    REDUCE(y)
    REDUCE(z)
    REDUCE(w)
    #undef REDUCE

    *reinterpret_cast<float4*>(out + i) = xo;
    *reinterpret_cast<float4*>(out + NPIX + i) = dm;
}

extern "C" void kernel_launch(void* const* d_in, const int* in_sizes, int n_in,
                              void* d_out, int out_size) {
    const float* z = (const float*)d_in[0];   // (15, 2048, 2048) fp32
    const float* v = (const float*)d_in[1];   // (16, 15) fp32
    float* out = (float*)d_out;               // [X (as float) | dmin], each NPIX

    const int nblocks = NPIX / (TPB * PPT);   // 4096
    gum_kernel<<<nblocks, TPB>>>(z, v, out);
}

// round 2
// speedup vs baseline: 1.0711x; 1.0711x over previous
#include <cuda_runtime.h>

#define KV 16
#define DIM 15
#define NPIX (2048 * 2048)
#define TPB 256
// one thread = 4 pixels, held as two f32x2 packed pairs

typedef unsigned long long u64;

__device__ __forceinline__ u64 ffma2(u64 a, u64 b, u64 c) {
    u64 d;
    asm("fma.rn.f32x2 %0, %1, %2, %3;" : "=l"(d) : "l"(a), "l"(b), "l"(c));
    return d;
}
__device__ __forceinline__ u64 pack2(float x, float y) {
    u64 p;
    asm("mov.b64 %0, {%1, %2};" : "=l"(p) : "f"(x), "f"(y));
    return p;
}
__device__ __forceinline__ void unpack2(u64 p, float& x, float& y) {
    asm("mov.b64 {%0, %1}, %2;" : "=f"(x), "=f"(y) : "l"(p));
}

// t_k = ||v_k||^2 - 2 v_k . z   (monotone in distance; argmin matches)
// dmin = sqrt(max(zz + t_min, 0))

__global__ __launch_bounds__(TPB) void gum_kernel(const float* __restrict__ z,
                                                  const float* __restrict__ v,
                                                  float* __restrict__ out) {
    __shared__ __align__(16) u64 ws2[KV][16];  // [k][j]: packed (-2v, -2v); j<15 used
    __shared__ u64 bp[KV];                     // packed (||v_k||^2, ||v_k||^2)

    const int t = threadIdx.x;
    if (t < KV * DIM) {
        int k = t / DIM;
        int j = t - k * DIM;
        float w = -2.0f * v[t];
        ws2[k][j] = pack2(w, w);
    }
    if (t < KV) {
        float s = 0.0f;
        #pragma unroll
        for (int j = 0; j < DIM; ++j) {
            float a = v[t * DIM + j];
            s = fmaf(a, a, s);
        }
        bp[t] = pack2(s, s);
    }
    __syncthreads();

    const size_t i4 = (size_t)blockIdx.x * TPB + t;  // float4 index
    const u64* zp = (const u64*)z;                   // view as f32x2 pairs

    // Front-batch all 15 global loads (MLP=15) — z reused across all 16 k
    u64 zlo[DIM], zhi[DIM];
    #pragma unroll
    for (int j = 0; j < DIM; ++j) {
        ulonglong2 zv = *(const ulonglong2*)(zp + (size_t)j * (NPIX / 2) + 2 * i4);
        zlo[j] = zv.x;  // pixels (i, i+1)
        zhi[j] = zv.y;  // pixels (i+2, i+3)
    }

    u64 zz_lo = 0ull, zz_hi = 0ull;  // bits of (0.0f, 0.0f)
    #pragma unroll
    for (int j = 0; j < DIM; ++j) {
        zz_lo = ffma2(zlo[j], zlo[j], zz_lo);
        zz_hi = ffma2(zhi[j], zhi[j], zz_hi);
    }

    float b0, b1, b2, b3;
    int i0 = 0, i1 = 0, i2 = 0, i3 = 0;

    #pragma unroll
    for (int k = 0; k < KV; ++k) {
        u64 bk = bp[k];
        u64 tlo = bk, thi = bk;
        #pragma unroll
        for (int j2 = 0; j2 < 7; ++j2) {
            ulonglong2 w = *(const ulonglong2*)&ws2[k][2 * j2];  // LDS.128: 2 pairs
            tlo = ffma2(w.x, zlo[2 * j2], tlo);
            thi = ffma2(w.x, zhi[2 * j2], thi);
            tlo = ffma2(w.y, zlo[2 * j2 + 1], tlo);
            thi = ffma2(w.y, zhi[2 * j2 + 1], thi);
        }
        {
            u64 w = ws2[k][14];
            tlo = ffma2(w, zlo[14], tlo);
            thi = ffma2(w, zhi[14], thi);
        }
        float t0, t1, t2, t3;
        unpack2(tlo, t0, t1);
        unpack2(thi, t2, t3);
        if (k == 0) {
            b0 = t0; b1 = t1; b2 = t2; b3 = t3;
        } else {
            // strict <, first-wins: matches jnp.argmin tie-breaking
            if (t0 < b0) { b0 = t0; i0 = k; }
            if (t1 < b1) { b1 = t1; i1 = k; }
            if (t2 < b2) { b2 = t2; i2 = k; }
            if (t3 < b3) { b3 = t3; i3 = k; }
        }
    }

    float zz0, zz1, zz2, zz3;
    unpack2(zz_lo, zz0, zz1);
    unpack2(zz_hi, zz2, zz3);

    float4 xo = make_float4((float)i0, (float)i1, (float)i2, (float)i3);
    float4 dm = make_float4(sqrtf(fmaxf(zz0 + b0, 0.0f)),
                            sqrtf(fmaxf(zz1 + b1, 0.0f)),
                            sqrtf(fmaxf(zz2 + b2, 0.0f)),
                            sqrtf(fmaxf(zz3 + b3, 0.0f)));

    *(float4*)(out + 4 * i4) = xo;
    *(float4*)(out + (size_t)NPIX + 4 * i4) = dm;
}

extern "C" void kernel_launch(void* const* d_in, const int* in_sizes, int n_in,
                              void* d_out, int out_size) {
    const float* z = (const float*)d_in[0];  // (15, 2048, 2048) fp32
    const float* v = (const float*)d_in[1];  // (16, 15) fp32
    float* out = (float*)d_out;              // [X (as float) | dmin], each NPIX

    const int nblocks = NPIX / (TPB * 4);    // 4096
    gum_kernel<<<nblocks, TPB>>>(z, v, out);
}

// round 3
// speedup vs baseline: 1.2370x; 1.1550x over previous
#include <cuda_runtime.h>

#define KV 16
#define DIM 15
#define NPIX (2048 * 2048)
#define TPB 256
// one thread = 4 pixels, held as two f32x2 packed pairs

typedef unsigned long long u64;

__device__ __forceinline__ u64 ffma2(u64 a, u64 b, u64 c) {
    u64 d;
    asm("fma.rn.f32x2 %0, %1, %2, %3;" : "=l"(d) : "l"(a), "l"(b), "l"(c));
    return d;
}
__device__ __forceinline__ u64 fadd2(u64 a, u64 b) {
    u64 d;
    asm("add.rn.f32x2 %0, %1, %2;" : "=l"(d) : "l"(a), "l"(b));
    return d;
}
__device__ __forceinline__ u64 pack2(float x, float y) {
    u64 p;
    asm("mov.b64 %0, {%1, %2};" : "=l"(p) : "f"(x), "f"(y));
    return p;
}
__device__ __forceinline__ void unpack2(u64 p, float& x, float& y) {
    asm("mov.b64 {%0, %1}, %2;" : "=f"(x), "=f"(y) : "l"(p));
}

// t_k = ||v_k||^2 - 2 v_k . z   (monotone in distance; argmin matches)
// dmin = sqrt(max(zz + t_min, 0))

__global__ __launch_bounds__(TPB) void gum_kernel(const float* __restrict__ z,
                                                  const float* __restrict__ v,
                                                  float* __restrict__ out) {
    __shared__ __align__(16) u64 ws2[KV][16];  // [k][j]: packed (-2v, -2v); j<15 used
    __shared__ u64 bp[KV];                     // packed (||v_k||^2, ||v_k||^2)

    const int t = threadIdx.x;
    if (t < KV * DIM) {
        int k = t / DIM;
        int j = t - k * DIM;
        float w = -2.0f * v[t];
        ws2[k][j] = pack2(w, w);
    }
    if (t < KV) {
        float s = 0.0f;
        #pragma unroll
        for (int j = 0; j < DIM; ++j) {
            float a = v[t * DIM + j];
            s = fmaf(a, a, s);
        }
        bp[t] = pack2(s, s);
    }
    __syncthreads();

    const size_t i4 = (size_t)blockIdx.x * TPB + t;  // float4 index
    const u64* zp = (const u64*)z;                   // view as f32x2 pairs

    // Front-batch all 15 global loads (MLP=15) — z reused across all 16 k
    u64 zlo[DIM], zhi[DIM];
    #pragma unroll
    for (int j = 0; j < DIM; ++j) {
        ulonglong2 zv = __ldcs((const ulonglong2*)(zp + (size_t)j * (NPIX / 2) + 2 * i4));
        zlo[j] = zv.x;  // pixels (i, i+1)
        zhi[j] = zv.y;  // pixels (i+2, i+3)
    }

    // ||z||^2 with split chains (depth 8 instead of 15)
    u64 zza_lo = 0ull, zzb_lo = 0ull, zza_hi = 0ull, zzb_hi = 0ull;
    #pragma unroll
    for (int j = 0; j < DIM; j += 2) {
        zza_lo = ffma2(zlo[j], zlo[j], zza_lo);
        zza_hi = ffma2(zhi[j], zhi[j], zza_hi);
        if (j + 1 < DIM) {
            zzb_lo = ffma2(zlo[j + 1], zlo[j + 1], zzb_lo);
            zzb_hi = ffma2(zhi[j + 1], zhi[j + 1], zzb_hi);
        }
    }
    u64 zz_lo = fadd2(zza_lo, zzb_lo);
    u64 zz_hi = fadd2(zza_hi, zzb_hi);

    float b0, b1, b2, b3;
    int i0 = 0, i1 = 0, i2 = 0, i3 = 0;

    #pragma unroll
    for (int k = 0; k < KV; ++k) {
        // 4 independent chains per k: (lo,hi) x (even-j, odd-j), depth <= 8
        u64 la = bp[k], lb = 0ull;
        u64 ha = bp[k], hb = 0ull;
        #pragma unroll
        for (int j2 = 0; j2 < 7; ++j2) {
            ulonglong2 w = *(const ulonglong2*)&ws2[k][2 * j2];  // LDS.128: 2 pairs
            la = ffma2(w.x, zlo[2 * j2], la);
            ha = ffma2(w.x, zhi[2 * j2], ha);
            lb = ffma2(w.y, zlo[2 * j2 + 1], lb);
            hb = ffma2(w.y, zhi[2 * j2 + 1], hb);
        }
        {
            u64 w = ws2[k][14];
            la = ffma2(w, zlo[14], la);
            ha = ffma2(w, zhi[14], ha);
        }
        u64 tlo = fadd2(la, lb);
        u64 thi = fadd2(ha, hb);

        float t0, t1, t2, t3;
        unpack2(tlo, t0, t1);
        unpack2(thi, t2, t3);
        if (k == 0) {
            b0 = t0; b1 = t1; b2 = t2; b3 = t3;
        } else {
            // strict <, first-wins: matches jnp.argmin tie-breaking
            if (t0 < b0) { b0 = t0; i0 = k; }
            if (t1 < b1) { b1 = t1; i1 = k; }
            if (t2 < b2) { b2 = t2; i2 = k; }
            if (t3 < b3) { b3 = t3; i3 = k; }
        }
    }

    float zz0, zz1, zz2, zz3;
    unpack2(zz_lo, zz0, zz1);
    unpack2(zz_hi, zz2, zz3);

    float4 xo = make_float4((float)i0, (float)i1, (float)i2, (float)i3);
    float4 dm = make_float4(sqrtf(fmaxf(zz0 + b0, 0.0f)),
                            sqrtf(fmaxf(zz1 + b1, 0.0f)),
                            sqrtf(fmaxf(zz2 + b2, 0.0f)),
                            sqrtf(fmaxf(zz3 + b3, 0.0f)));

    __stcs((float4*)(out + 4 * i4), xo);
    __stcs((float4*)(out + (size_t)NPIX + 4 * i4), dm);
}

extern "C" void kernel_launch(void* const* d_in, const int* in_sizes, int n_in,
                              void* d_out, int out_size) {
    const float* z = (const float*)d_in[0];  // (15, 2048, 2048) fp32
    const float* v = (const float*)d_in[1];  // (16, 15) fp32
    float* out = (float*)d_out;              // [X (as float) | dmin], each NPIX

    const int nblocks = NPIX / (TPB * 4);    // 4096
    gum_kernel<<<nblocks, TPB>>>(z, v, out);
}